// round 13
// baseline (speedup 1.0000x reference)
#include <cuda_runtime.h>

#define NUM_CAMS 6
#define C_FEAT   64
#define HF       16
#define WF       44
#define P_TOTAL  (8 * 128 * 128)                      // 131072
#define FEAT_ELEMS (NUM_CAMS * C_FEAT * HF * WF)      // 270336

#define PTS_PER_BLK 64          // 8 warps x 8 points, each warp autonomous
#define PTS_PER_WARP 8
#define WTASKS (PTS_PER_WARP * NUM_CAMS)              // 48 per warp

#define PK_BASE_MASK 0x7FFFF
#define PK_DX_BIT    (1 << 20)
#define PK_DY_BIT    (1 << 21)

// Precomputed per-camera projection (rows 0..2 of cam2img @ ego2cam)
__device__ float g_proj[NUM_CAMS][12];
// NHWC-transposed features: [cam][y][x][c], c contiguous (256B per pixel)
__device__ float g_feat_t[NUM_CAMS * HF * WF * C_FEAT];

// ---------------------------------------------------------------------------
// Prep: transpose (n,c,y,x) -> (n,y,x,c); block 0 also computes projections.
// ---------------------------------------------------------------------------
__global__ void prep_kernel(const float* __restrict__ in,
                            const float* __restrict__ ego2cam,
                            const float* __restrict__ cam2img) {
    int idx = blockIdx.x * blockDim.x + threadIdx.x;
    if (idx < FEAT_ELEMS) {
        int x = idx % WF;
        int t = idx / WF;
        int y = t % HF;  t /= HF;
        int c = t % C_FEAT;
        int n = t / C_FEAT;
        g_feat_t[(((n * HF + y) * WF) + x) * C_FEAT + c] = in[idx];
    }
    if (blockIdx.x == 0 && threadIdx.x < NUM_CAMS * 12) {
        int t = threadIdx.x;
        int n = t / 12;
        int r = (t % 12) / 4;
        int c = t % 4;
        float s = 0.f;
        #pragma unroll
        for (int k = 0; k < 4; k++)
            s += cam2img[n * 16 + r * 4 + k] * ego2cam[n * 16 + k * 4 + c];
        g_proj[n][r * 4 + c] = s;
    }
}

// ---------------------------------------------------------------------------
// Fuse, WARP-AUTONOMOUS: each warp owns 8 points end-to-end; zero block
// barriers (only __syncwarp). Stage-2 inner loop identical to the best (R10)
// fused A/B ILP structure.
// ---------------------------------------------------------------------------
__global__ void __launch_bounds__(256)
fuse_kernel(const float* __restrict__ vox, float* __restrict__ out) {
    __shared__ float4 s_w[8][WTASKS];           // 6 KB   per-warp [n*8+pt]
    __shared__ int    s_pk[8][WTASKS];          // 1.5 KB
    __shared__ int    s_mask[8][8];             // 256 B
    __shared__ float  s_out[PTS_PER_BLK][65];   // 16.6 KB (rows = global pt)

    int tid  = threadIdx.x;
    int lane = tid & 31;
    int w    = tid >> 5;                         // warp 0..7
    int pbase = blockIdx.x * PTS_PER_BLK;
    int wpt0  = w * PTS_PER_WARP;                // first local point of warp

    if (lane < PTS_PER_WARP) s_mask[w][lane] = 0;
    __syncwarp();

    // ---------------- Stage 1 (warp-local): 48 tasks over 32 lanes ----------
    #pragma unroll
    for (int k = 0; k < 2; k++) {
        int task = k * 32 + lane;
        if (task < WTASKS) {
            int pt = task & (PTS_PER_WARP - 1);
            int n  = task >> 3;                  // 0..5  (task = n*8+pt)
            int p  = pbase + wpt0 + pt;

            float px = vox[p];
            float py = vox[P_TOTAL + p];
            float pz = vox[2 * P_TOTAL + p];

            const float* M = g_proj[n];
            float uu = M[0] * px + M[1] * py + M[2]  * pz + M[3];
            float vv = M[4] * px + M[5] * py + M[6]  * pz + M[7];
            float dd = M[8] * px + M[9] * py + M[10] * pz + M[11];

            float inv = 1.0f / (dd + 1e-6f);
            float u = uu * inv;
            float v = vv * inv;

            bool valid = (dd > 0.1f) && (u >= 0.f) && (u <= 703.f)
                                     && (v >= 0.f) && (v <= 255.f);
            if (valid) {
                float x = u * (1.0f / 16.0f);
                float y = v * (1.0f / 16.0f);
                float x0f = floorf(x);
                float y0f = floorf(y);
                float wx1 = x - x0f, wy1 = y - y0f;
                float wx0 = 1.f - wx1, wy0 = 1.f - wy1;
                int x0 = (int)x0f;
                int y0 = (int)y0f;

                int dxb = PK_DX_BIT, dyb = PK_DY_BIT;
                if (x0 + 1 >= WF) { wx1 = 0.f; dxb = 0; }
                if (y0 + 1 >= HF) { wy1 = 0.f; dyb = 0; }

                int base = ((n * HF + y0) * WF + x0) * C_FEAT;   // < 2^19
                s_w[w][task]  = make_float4(wx0 * wy0, wx1 * wy0, wx0 * wy1, wx1 * wy1);
                s_pk[w][task] = base | dxb | dyb;
                atomicOr(&s_mask[w][pt], 1 << n);
            }
        }
    }
    __syncwarp();

    // ---------------- Stage 2: fused A/B pairs (R10 structure) --------------
    int half = lane >> 4;
    int l    = lane & 15;         // channel group
    const float* fB = g_feat_t + 4 * l;

    #pragma unroll
    for (int j = 0; j < 2; j++) {
        int lptA = j * 4 + half;          // local point 0..7
        int lptB = lptA + 2;
        int rowA = wpt0 + lptA;           // s_out row (global-in-block pt)
        int rowB = wpt0 + lptB;

        float4 accA = make_float4(0.f, 0.f, 0.f, 0.f);
        float4 accB = make_float4(0.f, 0.f, 0.f, 0.f);

        int mA = s_mask[w][lptA];
        int mB = s_mask[w][lptB];
        float rdenA = 1.0f / (float)__popc(mA | (mA == 0));
        float rdenB = 1.0f / (float)__popc(mB | (mB == 0));

        while (mA | mB) {
            // ---- issue A's loads ----
            float4 wgA; int baseA = 0, dxA = 0, dyA = 0; bool doA = (mA != 0);
            if (doA) {
                int n = __ffs(mA) - 1;
                mA &= mA - 1;
                int idx = n * PTS_PER_WARP + lptA;
                wgA = s_w[w][idx];
                int pk = s_pk[w][idx];
                baseA = pk & PK_BASE_MASK;
                dxA = (pk & PK_DX_BIT) ? C_FEAT : 0;
                dyA = (pk & PK_DY_BIT) ? WF * C_FEAT : 0;
            }
            // ---- issue B's loads ----
            float4 wgB; int baseB = 0, dxB = 0, dyB = 0; bool doB = (mB != 0);
            if (doB) {
                int n = __ffs(mB) - 1;
                mB &= mB - 1;
                int idx = n * PTS_PER_WARP + lptB;
                wgB = s_w[w][idx];
                int pk = s_pk[w][idx];
                baseB = pk & PK_BASE_MASK;
                dxB = (pk & PK_DX_BIT) ? C_FEAT : 0;
                dyB = (pk & PK_DY_BIT) ? WF * C_FEAT : 0;
            }

            if (doA) {
                float4 a = *(const float4*)(fB + baseA);
                float4 b = *(const float4*)(fB + baseA + dxA);
                float4 g = *(const float4*)(fB + baseA + dyA);
                float4 h = *(const float4*)(fB + baseA + dyA + dxA);
                accA.x = fmaf(wgA.x, a.x, fmaf(wgA.y, b.x, fmaf(wgA.z, g.x, fmaf(wgA.w, h.x, accA.x))));
                accA.y = fmaf(wgA.x, a.y, fmaf(wgA.y, b.y, fmaf(wgA.z, g.y, fmaf(wgA.w, h.y, accA.y))));
                accA.z = fmaf(wgA.x, a.z, fmaf(wgA.y, b.z, fmaf(wgA.z, g.z, fmaf(wgA.w, h.z, accA.z))));
                accA.w = fmaf(wgA.x, a.w, fmaf(wgA.y, b.w, fmaf(wgA.z, g.w, fmaf(wgA.w, h.w, accA.w))));
            }
            if (doB) {
                float4 a = *(const float4*)(fB + baseB);
                float4 b = *(const float4*)(fB + baseB + dxB);
                float4 g = *(const float4*)(fB + baseB + dyB);
                float4 h = *(const float4*)(fB + baseB + dyB + dxB);
                accB.x = fmaf(wgB.x, a.x, fmaf(wgB.y, b.x, fmaf(wgB.z, g.x, fmaf(wgB.w, h.x, accB.x))));
                accB.y = fmaf(wgB.x, a.y, fmaf(wgB.y, b.y, fmaf(wgB.z, g.y, fmaf(wgB.w, h.y, accB.y))));
                accB.z = fmaf(wgB.x, a.z, fmaf(wgB.y, b.z, fmaf(wgB.z, g.z, fmaf(wgB.w, h.z, accB.z))));
                accB.w = fmaf(wgB.x, a.w, fmaf(wgB.y, b.w, fmaf(wgB.z, g.w, fmaf(wgB.w, h.w, accB.w))));
            }
        }

        // scalar STS (row stride 65 floats: not 16B aligned for odd rows)
        s_out[rowA][4 * l + 0] = accA.x * rdenA;
        s_out[rowA][4 * l + 1] = accA.y * rdenA;
        s_out[rowA][4 * l + 2] = accA.z * rdenA;
        s_out[rowA][4 * l + 3] = accA.w * rdenA;
        s_out[rowB][4 * l + 0] = accB.x * rdenB;
        s_out[rowB][4 * l + 1] = accB.y * rdenB;
        s_out[rowB][4 * l + 2] = accB.z * rdenB;
        s_out[rowB][4 * l + 3] = accB.w * rdenB;
    }

    __syncwarp();

    // ---------------- Warp-local coalesced writeout -------------------------
    // This warp's 8 points x 64 channels; per channel 8 floats = 2 float4.
    // flat = k*32 + lane: c = flat>>1 (0..63), q = flat&1 (which float4).
    #pragma unroll
    for (int k = 0; k < 4; k++) {
        int flat = k * 32 + lane;
        int c = flat >> 1;
        int q = flat & 1;
        int r0 = wpt0 + 4 * q;
        float4 r;
        r.x = s_out[r0 + 0][c];
        r.y = s_out[r0 + 1][c];
        r.z = s_out[r0 + 2][c];
        r.w = s_out[r0 + 3][c];
        *(float4*)(out + c * P_TOTAL + pbase + wpt0 + 4 * q) = r;
    }
}

// ---------------------------------------------------------------------------
extern "C" void kernel_launch(void* const* d_in, const int* in_sizes, int n_in,
                              void* d_out, int out_size) {
    const float* img_feats = (const float*)d_in[0];   // (6,64,16,44)
    const float* ego2cam   = (const float*)d_in[1];   // (6,4,4)
    const float* cam2img   = (const float*)d_in[2];   // (6,4,4)
    const float* vox       = (const float*)d_in[3];   // (3,8,128,128)
    float* out = (float*)d_out;                       // (1,64,8,128,128)

    prep_kernel<<<(FEAT_ELEMS + 255) / 256, 256>>>(img_feats, ego2cam, cam2img);
    fuse_kernel<<<P_TOTAL / PTS_PER_BLK, 256>>>(vox, out);
}

// round 14
// speedup vs baseline: 1.1506x; 1.1506x over previous
#include <cuda_runtime.h>

#define NUM_CAMS 6
#define C_FEAT   64
#define HF       16
#define WF       44
#define P_TOTAL  (8 * 128 * 128)                      // 131072
#define FEAT_ELEMS (NUM_CAMS * C_FEAT * HF * WF)      // 270336

#define PTS_PER_BLK 64
#define TASKS (PTS_PER_BLK * NUM_CAMS)                // 384

#define PK_BASE_MASK 0x7FFFF
#define PK_DX_BIT    (1 << 20)
#define PK_DY_BIT    (1 << 21)

// Precomputed per-camera projection (rows 0..2 of cam2img @ ego2cam)
__device__ float g_proj[NUM_CAMS][12];
// NHWC-transposed features: [cam][y][x][c], c contiguous (256B per pixel)
__device__ float g_feat_t[NUM_CAMS * HF * WF * C_FEAT];

// ---------------------------------------------------------------------------
// Prep: transpose (n,c,y,x) -> (n,y,x,c); block 0 also computes projections.
// ---------------------------------------------------------------------------
__global__ void prep_kernel(const float* __restrict__ in,
                            const float* __restrict__ ego2cam,
                            const float* __restrict__ cam2img) {
    int idx = blockIdx.x * blockDim.x + threadIdx.x;
    if (idx < FEAT_ELEMS) {
        int x = idx % WF;
        int t = idx / WF;
        int y = t % HF;  t /= HF;
        int c = t % C_FEAT;
        int n = t / C_FEAT;
        g_feat_t[(((n * HF + y) * WF) + x) * C_FEAT + c] = in[idx];
    }
    if (blockIdx.x == 0 && threadIdx.x < NUM_CAMS * 12) {
        int t = threadIdx.x;
        int n = t / 12;
        int r = (t % 12) / 4;
        int c = t % 4;
        float s = 0.f;
        #pragma unroll
        for (int k = 0; k < 4; k++)
            s += cam2img[n * 16 + r * 4 + k] * ego2cam[n * 16 + k * 4 + c];
        g_proj[n][r * 4 + c] = s;
    }
}

// ---------------------------------------------------------------------------
// Fuse = R10 exactly, except: single 64-row s_out and ONE writeout pass,
// cutting block barriers 6 -> 3. Stage 1 and the stage-2 fused A/B loop are
// unchanged from the best-measured kernel.
// ---------------------------------------------------------------------------
__global__ void __launch_bounds__(256)
fuse_kernel(const float* __restrict__ vox, float* __restrict__ out) {
    __shared__ float4 s_w[TASKS];               // 6 KB    [n*64+pt]
    __shared__ int    s_pk[TASKS];              // 1.5 KB  [n*64+pt]
    __shared__ int    s_mask[PTS_PER_BLK];      // 256 B
    __shared__ float  s_out[64][65];            // 16.6 KB, padded rows

    int tid   = threadIdx.x;
    int pbase = blockIdx.x * PTS_PER_BLK;

    if (tid < PTS_PER_BLK) s_mask[tid] = 0;
    __syncthreads();                             // barrier 1

    // ---------------- Stage 1: projections, once per (point, cam) ----------
    for (int task = tid; task < TASKS; task += 256) {
        int pt = task & (PTS_PER_BLK - 1);
        int n  = task >> 6;                      // 0..5  (task = n*64+pt)
        int p  = pbase + pt;

        float px = vox[p];
        float py = vox[P_TOTAL + p];
        float pz = vox[2 * P_TOTAL + p];

        const float* M = g_proj[n];
        float uu = M[0] * px + M[1] * py + M[2]  * pz + M[3];
        float vv = M[4] * px + M[5] * py + M[6]  * pz + M[7];
        float dd = M[8] * px + M[9] * py + M[10] * pz + M[11];

        float inv = 1.0f / (dd + 1e-6f);
        float u = uu * inv;
        float v = vv * inv;

        bool valid = (dd > 0.1f) && (u >= 0.f) && (u <= 703.f)
                                 && (v >= 0.f) && (v <= 255.f);
        if (valid) {
            float x = u * (1.0f / 16.0f);
            float y = v * (1.0f / 16.0f);
            float x0f = floorf(x);
            float y0f = floorf(y);
            float wx1 = x - x0f, wy1 = y - y0f;
            float wx0 = 1.f - wx1, wy0 = 1.f - wy1;
            int x0 = (int)x0f;
            int y0 = (int)y0f;

            int dxb = PK_DX_BIT, dyb = PK_DY_BIT;
            if (x0 + 1 >= WF) { wx1 = 0.f; dxb = 0; }
            if (y0 + 1 >= HF) { wy1 = 0.f; dyb = 0; }

            int base = ((n * HF + y0) * WF + x0) * C_FEAT;   // < 2^19
            s_w[task]  = make_float4(wx0 * wy0, wx1 * wy0, wx0 * wy1, wx1 * wy1);
            s_pk[task] = base | dxb | dyb;
            atomicOr(&s_mask[pt], 1 << n);
        }
    }
    __syncthreads();                             // barrier 2

    // ---------------- Stage 2: fused A/B pairs (R10 loop, verbatim) ---------
    int lane = tid & 31;
    int wrp  = tid >> 5;          // 0..7
    int half = lane >> 4;
    int l    = lane & 15;         // channel group
    const float* fB = g_feat_t + 4 * l;

    #pragma unroll
    for (int chunk = 0; chunk < 2; chunk++) {
        int ptA = chunk * 32 + wrp * 4 + half;
        int ptB = ptA + 2;

        float4 accA = make_float4(0.f, 0.f, 0.f, 0.f);
        float4 accB = make_float4(0.f, 0.f, 0.f, 0.f);

        int mA = s_mask[ptA];
        int mB = s_mask[ptB];
        float rdenA = 1.0f / (float)__popc(mA | (mA == 0));
        float rdenB = 1.0f / (float)__popc(mB | (mB == 0));

        while (mA | mB) {
            // ---- issue A's loads ----
            float4 wgA; int baseA = 0, dxA = 0, dyA = 0; bool doA = (mA != 0);
            if (doA) {
                int n = __ffs(mA) - 1;
                mA &= mA - 1;
                int idx = n * PTS_PER_BLK + ptA;
                wgA = s_w[idx];
                int pk = s_pk[idx];
                baseA = pk & PK_BASE_MASK;
                dxA = (pk & PK_DX_BIT) ? C_FEAT : 0;
                dyA = (pk & PK_DY_BIT) ? WF * C_FEAT : 0;
            }
            // ---- issue B's loads ----
            float4 wgB; int baseB = 0, dxB = 0, dyB = 0; bool doB = (mB != 0);
            if (doB) {
                int n = __ffs(mB) - 1;
                mB &= mB - 1;
                int idx = n * PTS_PER_BLK + ptB;
                wgB = s_w[idx];
                int pk = s_pk[idx];
                baseB = pk & PK_BASE_MASK;
                dxB = (pk & PK_DX_BIT) ? C_FEAT : 0;
                dyB = (pk & PK_DY_BIT) ? WF * C_FEAT : 0;
            }

            if (doA) {
                float4 a = *(const float4*)(fB + baseA);
                float4 b = *(const float4*)(fB + baseA + dxA);
                float4 g = *(const float4*)(fB + baseA + dyA);
                float4 h = *(const float4*)(fB + baseA + dyA + dxA);
                accA.x = fmaf(wgA.x, a.x, fmaf(wgA.y, b.x, fmaf(wgA.z, g.x, fmaf(wgA.w, h.x, accA.x))));
                accA.y = fmaf(wgA.x, a.y, fmaf(wgA.y, b.y, fmaf(wgA.z, g.y, fmaf(wgA.w, h.y, accA.y))));
                accA.z = fmaf(wgA.x, a.z, fmaf(wgA.y, b.z, fmaf(wgA.z, g.z, fmaf(wgA.w, h.z, accA.z))));
                accA.w = fmaf(wgA.x, a.w, fmaf(wgA.y, b.w, fmaf(wgA.z, g.w, fmaf(wgA.w, h.w, accA.w))));
            }
            if (doB) {
                float4 a = *(const float4*)(fB + baseB);
                float4 b = *(const float4*)(fB + baseB + dxB);
                float4 g = *(const float4*)(fB + baseB + dyB);
                float4 h = *(const float4*)(fB + baseB + dyB + dxB);
                accB.x = fmaf(wgB.x, a.x, fmaf(wgB.y, b.x, fmaf(wgB.z, g.x, fmaf(wgB.w, h.x, accB.x))));
                accB.y = fmaf(wgB.x, a.y, fmaf(wgB.y, b.y, fmaf(wgB.z, g.y, fmaf(wgB.w, h.y, accB.y))));
                accB.z = fmaf(wgB.x, a.z, fmaf(wgB.y, b.z, fmaf(wgB.z, g.z, fmaf(wgB.w, h.z, accB.z))));
                accB.w = fmaf(wgB.x, a.w, fmaf(wgB.y, b.w, fmaf(wgB.z, g.w, fmaf(wgB.w, h.w, accB.w))));
            }
        }

        // scalar STS (row stride 65 floats: not 16B aligned for odd rows)
        s_out[ptA][4 * l + 0] = accA.x * rdenA;
        s_out[ptA][4 * l + 1] = accA.y * rdenA;
        s_out[ptA][4 * l + 2] = accA.z * rdenA;
        s_out[ptA][4 * l + 3] = accA.w * rdenA;
        s_out[ptB][4 * l + 0] = accB.x * rdenB;
        s_out[ptB][4 * l + 1] = accB.y * rdenB;
        s_out[ptB][4 * l + 2] = accB.z * rdenB;
        s_out[ptB][4 * l + 3] = accB.w * rdenB;
    }

    __syncthreads();                             // barrier 3

    // ---------------- Single coalesced vectorized writeout ------------------
    // 64 channels x 64 points; STG.128 along the point dimension.
    #pragma unroll
    for (int k = 0; k < 4; k++) {
        int flat = k * 256 + tid;           // 0..1023 float4 tiles
        int c = flat >> 4;                  // 0..63
        int q = flat & 15;                  // point quad 0..15
        float4 r;
        r.x = s_out[4 * q + 0][c];
        r.y = s_out[4 * q + 1][c];
        r.z = s_out[4 * q + 2][c];
        r.w = s_out[4 * q + 3][c];
        *(float4*)(out + c * P_TOTAL + pbase + 4 * q) = r;
    }
}

// ---------------------------------------------------------------------------
extern "C" void kernel_launch(void* const* d_in, const int* in_sizes, int n_in,
                              void* d_out, int out_size) {
    const float* img_feats = (const float*)d_in[0];   // (6,64,16,44)
    const float* ego2cam   = (const float*)d_in[1];   // (6,4,4)
    const float* cam2img   = (const float*)d_in[2];   // (6,4,4)
    const float* vox       = (const float*)d_in[3];   // (3,8,128,128)
    float* out = (float*)d_out;                       // (1,64,8,128,128)

    prep_kernel<<<(FEAT_ELEMS + 255) / 256, 256>>>(img_feats, ego2cam, cam2img);
    fuse_kernel<<<P_TOTAL / PTS_PER_BLK, 256>>>(vox, out);
}

// round 16
// speedup vs baseline: 1.1832x; 1.0284x over previous
#include <cuda_runtime.h>

#define NUM_CAMS 6
#define C_FEAT   64
#define HF       16
#define WF       44
#define P_TOTAL  (8 * 128 * 128)                      // 131072
#define FEAT_ELEMS (NUM_CAMS * C_FEAT * HF * WF)      // 270336

#define PTS_PER_BLK 64
#define TASKS (PTS_PER_BLK * NUM_CAMS)                // 384

// Precomputed per-camera projection (rows 0..2 of cam2img @ ego2cam)
__device__ float g_proj[NUM_CAMS][12];
// NHWC-transposed features: [cam][y][x][c], c contiguous (256B per pixel)
__device__ float g_feat_t[NUM_CAMS * HF * WF * C_FEAT];

// ---------------------------------------------------------------------------
// Prep: transpose (n,c,y,x) -> (n,y,x,c); block 0 also computes projections.
// ---------------------------------------------------------------------------
__global__ void prep_kernel(const float* __restrict__ in,
                            const float* __restrict__ ego2cam,
                            const float* __restrict__ cam2img) {
    int idx = blockIdx.x * blockDim.x + threadIdx.x;
    if (idx < FEAT_ELEMS) {
        int x = idx % WF;
        int t = idx / WF;
        int y = t % HF;  t /= HF;
        int c = t % C_FEAT;
        int n = t / C_FEAT;
        g_feat_t[(((n * HF + y) * WF) + x) * C_FEAT + c] = in[idx];
    }
    if (blockIdx.x == 0 && threadIdx.x < NUM_CAMS * 12) {
        int t = threadIdx.x;
        int n = t / 12;
        int r = (t % 12) / 4;
        int c = t % 4;
        float s = 0.f;
        #pragma unroll
        for (int k = 0; k < 4; k++)
            s += cam2img[n * 16 + r * 4 + k] * ego2cam[n * 16 + k * 4 + c];
        g_proj[n][r * 4 + c] = s;
    }
}

// ---------------------------------------------------------------------------
// Fuse = R10 structure; single change: stage 1 stores all four ABSOLUTE
// corner offsets (int4), so stage 2's address chain is LDS.128 -> add -> LDG
// (no bitfield decode on the critical path).
// ---------------------------------------------------------------------------
__global__ void __launch_bounds__(256)
fuse_kernel(const float* __restrict__ vox, float* __restrict__ out) {
    __shared__ float4 s_w[TASKS];               // 6 KB    [n*64+pt]
    __shared__ int4   s_offs[TASKS];            // 6 KB    [n*64+pt]
    __shared__ int    s_mask[PTS_PER_BLK];      // 256 B
    __shared__ float  s_out[32][65];            // 8.25 KB, padded rows

    int tid   = threadIdx.x;
    int pbase = blockIdx.x * PTS_PER_BLK;

    if (tid < PTS_PER_BLK) s_mask[tid] = 0;
    __syncthreads();

    // ---------------- Stage 1: projections, once per (point, cam) ----------
    for (int task = tid; task < TASKS; task += 256) {
        int pt = task & (PTS_PER_BLK - 1);
        int n  = task >> 6;                      // 0..5  (task = n*64+pt)
        int p  = pbase + pt;

        float px = vox[p];
        float py = vox[P_TOTAL + p];
        float pz = vox[2 * P_TOTAL + p];

        const float* M = g_proj[n];
        float uu = M[0] * px + M[1] * py + M[2]  * pz + M[3];
        float vv = M[4] * px + M[5] * py + M[6]  * pz + M[7];
        float dd = M[8] * px + M[9] * py + M[10] * pz + M[11];

        float inv = 1.0f / (dd + 1e-6f);
        float u = uu * inv;
        float v = vv * inv;

        bool valid = (dd > 0.1f) && (u >= 0.f) && (u <= 703.f)
                                 && (v >= 0.f) && (v <= 255.f);
        if (valid) {
            float x = u * (1.0f / 16.0f);
            float y = v * (1.0f / 16.0f);
            float x0f = floorf(x);
            float y0f = floorf(y);
            float wx1 = x - x0f, wy1 = y - y0f;
            float wx0 = 1.f - wx1, wy0 = 1.f - wy1;
            int x0 = (int)x0f;
            int y0 = (int)y0f;

            int dx = C_FEAT, dy = WF * C_FEAT;
            if (x0 + 1 >= WF) { wx1 = 0.f; dx = 0; }
            if (y0 + 1 >= HF) { wy1 = 0.f; dy = 0; }

            int base = ((n * HF + y0) * WF + x0) * C_FEAT;
            s_w[task]    = make_float4(wx0 * wy0, wx1 * wy0, wx0 * wy1, wx1 * wy1);
            s_offs[task] = make_int4(base, base + dx, base + dy, base + dy + dx);
            atomicOr(&s_mask[pt], 1 << n);
        }
    }
    __syncthreads();

    // ---------------- Stage 2 + writeout, 2 chunks of 32 points -------------
    int lane = tid & 31;
    int wrp  = tid >> 5;          // 0..7
    int half = lane >> 4;
    int l    = lane & 15;         // channel group
    const float* fB = g_feat_t + 4 * l;

    #pragma unroll
    for (int chunk = 0; chunk < 2; chunk++) {
        // Each thread owns two points; their cam loops are FUSED so the two
        // independent LDS->LDG->FMA chains interleave (2x MLP).
        int ptA = chunk * 32 + wrp * 4 + half;       // it=0 point
        int ptB = ptA + 2;                            // it=1 point
        int rowA = ptA - chunk * 32;
        int rowB = ptB - chunk * 32;

        float4 accA = make_float4(0.f, 0.f, 0.f, 0.f);
        float4 accB = make_float4(0.f, 0.f, 0.f, 0.f);

        int mA = s_mask[ptA];
        int mB = s_mask[ptB];
        float rdenA = 1.0f / (float)__popc(mA | (mA == 0));
        float rdenB = 1.0f / (float)__popc(mB | (mB == 0));

        while (mA | mB) {
            // ---- issue A's loads ----
            float4 wgA; int4 oA = make_int4(0, 0, 0, 0); bool doA = (mA != 0);
            if (doA) {
                int n = __ffs(mA) - 1;
                mA &= mA - 1;
                int idx = n * PTS_PER_BLK + ptA;
                wgA = s_w[idx];
                oA  = s_offs[idx];
            }
            // ---- issue B's loads ----
            float4 wgB; int4 oB = make_int4(0, 0, 0, 0); bool doB = (mB != 0);
            if (doB) {
                int n = __ffs(mB) - 1;
                mB &= mB - 1;
                int idx = n * PTS_PER_BLK + ptB;
                wgB = s_w[idx];
                oB  = s_offs[idx];
            }

            if (doA) {
                float4 a = *(const float4*)(fB + oA.x);
                float4 b = *(const float4*)(fB + oA.y);
                float4 g = *(const float4*)(fB + oA.z);
                float4 h = *(const float4*)(fB + oA.w);
                accA.x = fmaf(wgA.x, a.x, fmaf(wgA.y, b.x, fmaf(wgA.z, g.x, fmaf(wgA.w, h.x, accA.x))));
                accA.y = fmaf(wgA.x, a.y, fmaf(wgA.y, b.y, fmaf(wgA.z, g.y, fmaf(wgA.w, h.y, accA.y))));
                accA.z = fmaf(wgA.x, a.z, fmaf(wgA.y, b.z, fmaf(wgA.z, g.z, fmaf(wgA.w, h.z, accA.z))));
                accA.w = fmaf(wgA.x, a.w, fmaf(wgA.y, b.w, fmaf(wgA.z, g.w, fmaf(wgA.w, h.w, accA.w))));
            }
            if (doB) {
                float4 a = *(const float4*)(fB + oB.x);
                float4 b = *(const float4*)(fB + oB.y);
                float4 g = *(const float4*)(fB + oB.z);
                float4 h = *(const float4*)(fB + oB.w);
                accB.x = fmaf(wgB.x, a.x, fmaf(wgB.y, b.x, fmaf(wgB.z, g.x, fmaf(wgB.w, h.x, accB.x))));
                accB.y = fmaf(wgB.x, a.y, fmaf(wgB.y, b.y, fmaf(wgB.z, g.y, fmaf(wgB.w, h.y, accB.y))));
                accB.z = fmaf(wgB.x, a.z, fmaf(wgB.y, b.z, fmaf(wgB.z, g.z, fmaf(wgB.w, h.z, accB.z))));
                accB.w = fmaf(wgB.x, a.w, fmaf(wgB.y, b.w, fmaf(wgB.z, g.w, fmaf(wgB.w, h.w, accB.w))));
            }
        }

        // scalar STS (row stride 65 floats: not 16B aligned for odd rows)
        s_out[rowA][4 * l + 0] = accA.x * rdenA;
        s_out[rowA][4 * l + 1] = accA.y * rdenA;
        s_out[rowA][4 * l + 2] = accA.z * rdenA;
        s_out[rowA][4 * l + 3] = accA.w * rdenA;
        s_out[rowB][4 * l + 0] = accB.x * rdenB;
        s_out[rowB][4 * l + 1] = accB.y * rdenB;
        s_out[rowB][4 * l + 2] = accB.z * rdenB;
        s_out[rowB][4 * l + 3] = accB.w * rdenB;

        __syncthreads();

        // Coalesced vectorized writeout of this 32-point chunk:
        // 64 channels x 32 points, STG.128 along the point dimension.
        #pragma unroll
        for (int k = 0; k < 2; k++) {
            int flat = k * 256 + tid;       // 0..511 float4 tiles
            int c = flat >> 3;              // 0..63
            int q = flat & 7;               // point quad 0..7
            float4 r;
            r.x = s_out[4 * q + 0][c];
            r.y = s_out[4 * q + 1][c];
            r.z = s_out[4 * q + 2][c];
            r.w = s_out[4 * q + 3][c];
            *(float4*)(out + c * P_TOTAL + pbase + chunk * 32 + 4 * q) = r;
        }

        __syncthreads();   // protect s_out before next chunk's STS
    }
}

// ---------------------------------------------------------------------------
extern "C" void kernel_launch(void* const* d_in, const int* in_sizes, int n_in,
                              void* d_out, int out_size) {
    const float* img_feats = (const float*)d_in[0];   // (6,64,16,44)
    const float* ego2cam   = (const float*)d_in[1];   // (6,4,4)
    const float* cam2img   = (const float*)d_in[2];   // (6,4,4)
    const float* vox       = (const float*)d_in[3];   // (3,8,128,128)
    float* out = (float*)d_out;                       // (1,64,8,128,128)

    prep_kernel<<<(FEAT_ELEMS + 255) / 256, 256>>>(img_feats, ego2cam, cam2img);
    fuse_kernel<<<P_TOTAL / PTS_PER_BLK, 256>>>(vox, out);
}

// round 17
// speedup vs baseline: 1.3723x; 1.1598x over previous
#include <cuda_runtime.h>

#define NUM_CAMS 6
#define C_FEAT   64
#define HF       16
#define WF       44
#define NPIX     (HF * WF)                            // 704
#define P_TOTAL  (8 * 128 * 128)                      // 131072

#define PTS_PER_BLK 64
#define TASKS (PTS_PER_BLK * NUM_CAMS)                // 384

#define PK_BASE_MASK 0x7FFFF
#define PK_DX_BIT    (1 << 20)
#define PK_DY_BIT    (1 << 21)

// NHWC-transposed features: [cam][y][x][c], c contiguous (256B per pixel)
__device__ float g_feat_t[NUM_CAMS * NPIX * C_FEAT];

// ---------------------------------------------------------------------------
// Prep: tiled transpose (n,c,pix) -> (n,pix,c), both sides 256B-coalesced.
// Grid: NUM_CAMS * (NPIX/64) = 66 blocks of 256 threads.
// ---------------------------------------------------------------------------
__global__ void prep_kernel(const float* __restrict__ in) {
    __shared__ float t[64][65];
    int n    = blockIdx.x / (NPIX / 64);
    int tile = blockIdx.x % (NPIX / 64);
    int pix0 = tile * 64;
    int tid  = threadIdx.x;

    // Load: 64 c-rows x 64 pix, coalesced along pix.
    #pragma unroll
    for (int k = 0; k < 16; k++) {
        int flat = k * 256 + tid;           // 0..4095
        int c   = flat >> 6;                // 0..63
        int pix = flat & 63;
        t[pix][c] = in[(n * C_FEAT + c) * NPIX + pix0 + pix];
    }
    __syncthreads();

    // Store: 64 pix-rows x 64 c, coalesced along c (256B per pixel).
    #pragma unroll
    for (int k = 0; k < 16; k++) {
        int flat = k * 256 + tid;
        int pix = flat >> 6;
        int c   = flat & 63;
        g_feat_t[(n * NPIX + pix0 + pix) * C_FEAT + c] = t[pix][c];
    }
}

// ---------------------------------------------------------------------------
// Fuse = R10 (best measured) with one addition: each block computes the
// 6 camera projection matrices itself into smem (72 threads x 4 FMAs),
// removing the separate proj kernel / global round-trip.
// ---------------------------------------------------------------------------
__global__ void __launch_bounds__(256)
fuse_kernel(const float* __restrict__ vox, float* __restrict__ out,
            const float* __restrict__ ego2cam, const float* __restrict__ cam2img) {
    __shared__ float  s_proj[NUM_CAMS][12];     // 288 B
    __shared__ float4 s_w[TASKS];               // 6 KB    [n*64+pt]
    __shared__ int    s_pk[TASKS];              // 1.5 KB  [n*64+pt]
    __shared__ int    s_mask[PTS_PER_BLK];      // 256 B
    __shared__ float  s_out[32][65];            // 8.25 KB, padded rows

    int tid   = threadIdx.x;
    int pbase = blockIdx.x * PTS_PER_BLK;

    if (tid < PTS_PER_BLK) s_mask[tid] = 0;
    if (tid < NUM_CAMS * 12) {
        int n = tid / 12;
        int r = (tid % 12) / 4;
        int c = tid % 4;
        float s = 0.f;
        #pragma unroll
        for (int k = 0; k < 4; k++)
            s += cam2img[n * 16 + r * 4 + k] * ego2cam[n * 16 + k * 4 + c];
        s_proj[n][r * 4 + c] = s;
    }
    __syncthreads();

    // ---------------- Stage 1: projections, once per (point, cam) ----------
    for (int task = tid; task < TASKS; task += 256) {
        int pt = task & (PTS_PER_BLK - 1);
        int n  = task >> 6;                      // 0..5  (task = n*64+pt)
        int p  = pbase + pt;

        float px = vox[p];
        float py = vox[P_TOTAL + p];
        float pz = vox[2 * P_TOTAL + p];

        const float* M = s_proj[n];
        float uu = M[0] * px + M[1] * py + M[2]  * pz + M[3];
        float vv = M[4] * px + M[5] * py + M[6]  * pz + M[7];
        float dd = M[8] * px + M[9] * py + M[10] * pz + M[11];

        float inv = 1.0f / (dd + 1e-6f);
        float u = uu * inv;
        float v = vv * inv;

        bool valid = (dd > 0.1f) && (u >= 0.f) && (u <= 703.f)
                                 && (v >= 0.f) && (v <= 255.f);
        if (valid) {
            float x = u * (1.0f / 16.0f);
            float y = v * (1.0f / 16.0f);
            float x0f = floorf(x);
            float y0f = floorf(y);
            float wx1 = x - x0f, wy1 = y - y0f;
            float wx0 = 1.f - wx1, wy0 = 1.f - wy1;
            int x0 = (int)x0f;
            int y0 = (int)y0f;

            int dxb = PK_DX_BIT, dyb = PK_DY_BIT;
            if (x0 + 1 >= WF) { wx1 = 0.f; dxb = 0; }
            if (y0 + 1 >= HF) { wy1 = 0.f; dyb = 0; }

            int base = ((n * HF + y0) * WF + x0) * C_FEAT;   // < 2^19
            s_w[task]  = make_float4(wx0 * wy0, wx1 * wy0, wx0 * wy1, wx1 * wy1);
            s_pk[task] = base | dxb | dyb;
            atomicOr(&s_mask[pt], 1 << n);
        }
    }
    __syncthreads();

    // ---------------- Stage 2 + writeout, 2 chunks of 32 points -------------
    int lane = tid & 31;
    int wrp  = tid >> 5;          // 0..7
    int half = lane >> 4;
    int l    = lane & 15;         // channel group
    const float* fB = g_feat_t + 4 * l;

    #pragma unroll
    for (int chunk = 0; chunk < 2; chunk++) {
        // Each thread owns two points; their cam loops are FUSED so the two
        // independent LDS->LDG->FMA chains interleave (2x MLP).
        int ptA = chunk * 32 + wrp * 4 + half;       // it=0 point
        int ptB = ptA + 2;                            // it=1 point
        int rowA = ptA - chunk * 32;
        int rowB = ptB - chunk * 32;

        float4 accA = make_float4(0.f, 0.f, 0.f, 0.f);
        float4 accB = make_float4(0.f, 0.f, 0.f, 0.f);

        int mA = s_mask[ptA];
        int mB = s_mask[ptB];
        float rdenA = 1.0f / (float)__popc(mA | (mA == 0));
        float rdenB = 1.0f / (float)__popc(mB | (mB == 0));

        while (mA | mB) {
            // ---- issue A's loads ----
            float4 wgA; int baseA = 0, dxA = 0, dyA = 0; bool doA = (mA != 0);
            if (doA) {
                int n = __ffs(mA) - 1;
                mA &= mA - 1;
                int idx = n * PTS_PER_BLK + ptA;
                wgA = s_w[idx];
                int pk = s_pk[idx];
                baseA = pk & PK_BASE_MASK;
                dxA = (pk & PK_DX_BIT) ? C_FEAT : 0;
                dyA = (pk & PK_DY_BIT) ? WF * C_FEAT : 0;
            }
            // ---- issue B's loads ----
            float4 wgB; int baseB = 0, dxB = 0, dyB = 0; bool doB = (mB != 0);
            if (doB) {
                int n = __ffs(mB) - 1;
                mB &= mB - 1;
                int idx = n * PTS_PER_BLK + ptB;
                wgB = s_w[idx];
                int pk = s_pk[idx];
                baseB = pk & PK_BASE_MASK;
                dxB = (pk & PK_DX_BIT) ? C_FEAT : 0;
                dyB = (pk & PK_DY_BIT) ? WF * C_FEAT : 0;
            }

            if (doA) {
                float4 a = *(const float4*)(fB + baseA);
                float4 b = *(const float4*)(fB + baseA + dxA);
                float4 g = *(const float4*)(fB + baseA + dyA);
                float4 h = *(const float4*)(fB + baseA + dyA + dxA);
                accA.x = fmaf(wgA.x, a.x, fmaf(wgA.y, b.x, fmaf(wgA.z, g.x, fmaf(wgA.w, h.x, accA.x))));
                accA.y = fmaf(wgA.x, a.y, fmaf(wgA.y, b.y, fmaf(wgA.z, g.y, fmaf(wgA.w, h.y, accA.y))));
                accA.z = fmaf(wgA.x, a.z, fmaf(wgA.y, b.z, fmaf(wgA.z, g.z, fmaf(wgA.w, h.z, accA.z))));
                accA.w = fmaf(wgA.x, a.w, fmaf(wgA.y, b.w, fmaf(wgA.z, g.w, fmaf(wgA.w, h.w, accA.w))));
            }
            if (doB) {
                float4 a = *(const float4*)(fB + baseB);
                float4 b = *(const float4*)(fB + baseB + dxB);
                float4 g = *(const float4*)(fB + baseB + dyB);
                float4 h = *(const float4*)(fB + baseB + dyB + dxB);
                accB.x = fmaf(wgB.x, a.x, fmaf(wgB.y, b.x, fmaf(wgB.z, g.x, fmaf(wgB.w, h.x, accB.x))));
                accB.y = fmaf(wgB.x, a.y, fmaf(wgB.y, b.y, fmaf(wgB.z, g.y, fmaf(wgB.w, h.y, accB.y))));
                accB.z = fmaf(wgB.x, a.z, fmaf(wgB.y, b.z, fmaf(wgB.z, g.z, fmaf(wgB.w, h.z, accB.z))));
                accB.w = fmaf(wgB.x, a.w, fmaf(wgB.y, b.w, fmaf(wgB.z, g.w, fmaf(wgB.w, h.w, accB.w))));
            }
        }

        // scalar STS (row stride 65 floats: not 16B aligned for odd rows)
        s_out[rowA][4 * l + 0] = accA.x * rdenA;
        s_out[rowA][4 * l + 1] = accA.y * rdenA;
        s_out[rowA][4 * l + 2] = accA.z * rdenA;
        s_out[rowA][4 * l + 3] = accA.w * rdenA;
        s_out[rowB][4 * l + 0] = accB.x * rdenB;
        s_out[rowB][4 * l + 1] = accB.y * rdenB;
        s_out[rowB][4 * l + 2] = accB.z * rdenB;
        s_out[rowB][4 * l + 3] = accB.w * rdenB;

        __syncthreads();

        // Coalesced vectorized writeout of this 32-point chunk:
        // 64 channels x 32 points, STG.128 along the point dimension.
        #pragma unroll
        for (int k = 0; k < 2; k++) {
            int flat = k * 256 + tid;       // 0..511 float4 tiles
            int c = flat >> 3;              // 0..63
            int q = flat & 7;               // point quad 0..7
            float4 r;
            r.x = s_out[4 * q + 0][c];
            r.y = s_out[4 * q + 1][c];
            r.z = s_out[4 * q + 2][c];
            r.w = s_out[4 * q + 3][c];
            *(float4*)(out + c * P_TOTAL + pbase + chunk * 32 + 4 * q) = r;
        }

        __syncthreads();   // protect s_out before next chunk's STS
    }
}

// ---------------------------------------------------------------------------
extern "C" void kernel_launch(void* const* d_in, const int* in_sizes, int n_in,
                              void* d_out, int out_size) {
    const float* img_feats = (const float*)d_in[0];   // (6,64,16,44)
    const float* ego2cam   = (const float*)d_in[1];   // (6,4,4)
    const float* cam2img   = (const float*)d_in[2];   // (6,4,4)
    const float* vox       = (const float*)d_in[3];   // (3,8,128,128)
    float* out = (float*)d_out;                       // (1,64,8,128,128)

    prep_kernel<<<NUM_CAMS * (NPIX / 64), 256>>>(img_feats);
    fuse_kernel<<<P_TOTAL / PTS_PER_BLK, 256>>>(vox, out, ego2cam, cam2img);
}